// round 15
// baseline (speedup 1.0000x reference)
#include <cuda_runtime.h>

// tiles: (154, 7, 28, 16, 16, 16) fp32
// occupancy: (8,8,8) bool (encoding auto-detected)
// output: (7, 1, 28, 64, 64, 64) fp32 == (196, 64, 64, 64), window offset 8, 5x5x5 tiles
#define NT 5
#define OFF 8
#define JC 196
#define NC 28                  // c = 0..27; j = 0..6 (jc = j*28 + c)
#define TILE_STRIDE 4096       // 16^3 floats per (tile,jc) slab
#define OUT_JC_F 262144        // 64*64*64 floats per jc
// Each thread: one z-pair (32B, LDG.256/STG.256) per j. zp in low 3 bits ->
// warp stores 4 y-rows x 256B = 1024B dense segments.
#define N_THREADS (NC * 64 * 64 * 8)    // 917,504 -> 3584 blocks

__device__ int g_lut[NT * NT * NT];
// 0 initially. Block 0 recomputes g_lut from the inputs on EVERY call, then
// sets the flag; other blocks wait. After call 1 the flag stays set; rewrite
// races are benign (identical values from identical inputs) -> output never
// depends on call history.
__device__ unsigned int g_flag;

__device__ __forceinline__ void ldg256(const float* p, float* r) {
    asm volatile("ld.global.nc.v8.f32 {%0,%1,%2,%3,%4,%5,%6,%7}, [%8];"
                 : "=f"(r[0]), "=f"(r[1]), "=f"(r[2]), "=f"(r[3]),
                   "=f"(r[4]), "=f"(r[5]), "=f"(r[6]), "=f"(r[7])
                 : "l"(p));
}
__device__ __forceinline__ void stg256(float* p, const float* r) {
    asm volatile("st.global.cs.v8.f32 [%0], {%1,%2,%3,%4,%5,%6,%7,%8};"
                 :: "l"(p),
                    "f"(r[0]), "f"(r[1]), "f"(r[2]), "f"(r[3]),
                    "f"(r[4]), "f"(r[5]), "f"(r[6]), "f"(r[7])
                 : "memory");
}

__global__ void __launch_bounds__(256) gather_kernel(
    const float* __restrict__ tiles,
    const unsigned char* __restrict__ occ_raw,
    float* __restrict__ out) {

    const int t = threadIdx.x;

    if (blockIdx.x == 0) {
        // ---- build LUT: ballot/popcount over 512 cells (threads t, t+256) ----
        __shared__ unsigned int words[16];
        __shared__ int wsum[8];
        __shared__ int enc_bytes;
        const int warp = t >> 5, lane = t & 31;

        const int b0 = occ_raw[t];
        const int b1 = occ_raw[t + 256];
        int s = b0 + b1;
        #pragma unroll
        for (int o = 16; o > 0; o >>= 1) s += __shfl_down_sync(0xffffffffu, s, o);
        if (lane == 0) wsum[warp] = s;
        __syncthreads();
        if (t == 0) {
            int tot = 0;
            #pragma unroll
            for (int i = 0; i < 8; i++) tot += wsum[i];
            // byte-bool: byte sum == 154 (>128). widened 32-bit: first 512
            // bytes cover 128 cells -> byte sum <= 128.
            enc_bytes = (tot > 128) ? 1 : 0;
        }
        __syncthreads();

        int v0, v1;
        if (enc_bytes) {
            v0 = (b0 != 0); v1 = (b1 != 0);
        } else {
            const unsigned int* w32 = reinterpret_cast<const unsigned int*>(occ_raw);
            v0 = (w32[t] != 0u); v1 = (w32[t + 256] != 0u);
        }
        const unsigned int bal0 = __ballot_sync(0xffffffffu, v0);
        const unsigned int bal1 = __ballot_sync(0xffffffffu, v1);
        if (lane == 0) { words[warp] = bal0; words[warp + 8] = bal1; }
        __syncthreads();

        const unsigned int lmask = (1u << lane) - 1u;
        int pre0 = 0, pre1 = 0;
        #pragma unroll
        for (int i = 0; i < 16; i++) {
            const int p = __popc(words[i]);
            pre0 += (i < warp) ? p : 0;
            pre1 += (i < warp + 8) ? p : 0;
        }
        const int idx0 = pre0 + __popc(words[warp] & lmask);
        const int idx1 = pre1 + __popc(words[warp + 8] & lmask);

        {
            int cx = t >> 6, cy = (t >> 3) & 7, cz = t & 7;
            if (cx < NT && cy < NT && cz < NT)
                g_lut[(cx * NT + cy) * NT + cz] = v0 ? idx0 : -1;
            const int u = t + 256;
            cx = u >> 6; cy = (u >> 3) & 7; cz = u & 7;
            if (cx < NT && cy < NT && cz < NT)
                g_lut[(cx * NT + cy) * NT + cz] = v1 ? idx1 : -1;
        }
        __syncthreads();
        if (t == 0) {
            __threadfence();
            atomicExch(&g_flag, 1u);     // release: LUT visible before flag
        }
        __syncthreads();
    } else {
        if (t == 0) {
            // acquire: volatile L2 read poll (no L1 caching, no atomic spam)
            const volatile unsigned int* f = &g_flag;
            while (*f == 0u) __nanosleep(64);
        }
        __syncthreads();
    }

    // ---- gather: one z-pair (32B) per j, 7 j-channels ----
    const int id = blockIdx.x * 256 + t;   // < 917,504

    const int zp = id & 7;               // z-pair: floats z = 8*zp .. 8*zp+7
    int tmp = id >> 3;
    const int y = tmp & 63;  tmp >>= 6;
    const int x = tmp & 63;  tmp >>= 6;
    const int c = tmp;                   // 0..27

    const int gz = (zp << 3) + OFF;      // pair stays inside one tile; iz in {0,8}
    const int gy = y + OFF;
    const int gx = x + OFF;
    const int tz = gz >> 4, iz = gz & 15;
    const int ty = gy >> 4, iy = gy & 15;
    const int tx = gx >> 4, ix = gx & 15;

    const int tidx = g_lut[(tx * NT + ty) * NT + tz];
    const int spatial_src = (ix << 8) + (iy << 4) + iz;      // float offset, 32B-aligned
    const int spatial_out = (x << 12) + (y << 6) + (zp << 3); // float offset, 32B-aligned

    float* o = out + spatial_out + (size_t)c * OUT_JC_F;
    const size_t ot = (size_t)NC * OUT_JC_F;                 // float stride per j

    if (tidx >= 0) {
        const float* base = tiles + (size_t)(tidx * JC + c) * TILE_STRIDE + spatial_src;
        const size_t st = (size_t)NC * TILE_STRIDE;          // float stride per j
        // pairs of j: 2 LDG.256 in flight, then 2 STG.256 (16 payload regs live)
        #pragma unroll
        for (int j = 0; j < 6; j += 2) {
            float a[8], b[8];
            ldg256(base + j * st, a);
            ldg256(base + (j + 1) * st, b);
            stg256(o + j * ot, a);
            stg256(o + (j + 1) * ot, b);
        }
        float tail[8];
        ldg256(base + 6 * st, tail);
        stg256(o + 6 * ot, tail);
    } else {
        float z[8] = {0.f, 0.f, 0.f, 0.f, 0.f, 0.f, 0.f, 0.f};
        #pragma unroll
        for (int j = 0; j < 7; j++) stg256(o + j * ot, z);
    }
}

extern "C" void kernel_launch(void* const* d_in, const int* in_sizes, int n_in,
                              void* d_out, int out_size) {
    const float* tiles = (const float*)d_in[0];
    const unsigned char* occ = (const unsigned char*)d_in[1];

    gather_kernel<<<N_THREADS / 256, 256>>>(tiles, occ, (float*)d_out);
}

// round 16
// speedup vs baseline: 1.1133x; 1.1133x over previous
#include <cuda_runtime.h>

// tiles: (154, 7, 28, 16, 16, 16) fp32
// occupancy: (8,8,8) bool (encoding auto-detected)
// output: (7, 1, 28, 64, 64, 64) fp32 == (196, 64, 64, 64), window offset 8, 5x5x5 tiles
#define NT 5
#define OFF 8
#define JC 196
#define NC 28                 // c = 0..27 in thread id; j = 0..6 unrolled (MLP=7)
#define TILE_STRIDE 4096      // 16^3 floats per (tile,jc) slab
#define OUT_JC_F4 65536       // 64*64*64/4 float4 per jc
#define N_THREADS (NC * 64 * 64 * 16)   // 1,835,008 -> 3584 blocks of 512

// Single launch, no flag, no second kernel: every block derives its threads'
// LUT entries inline from the 512-byte occupancy (L2-resident after wave 1).
// Prologue: 1 byte/thread + __syncthreads_count + warp ballots + 16-word scan.
__global__ void __launch_bounds__(512) gather_kernel(
    const float* __restrict__ tiles,
    const unsigned char* __restrict__ occ_raw,
    float4* __restrict__ out) {

    __shared__ unsigned int words[16];   // occupancy bitmap, cell = bit
    __shared__ int pre[16];              // exclusive prefix popcount per word

    const int t = threadIdx.x;           // 0..511 == occupancy cell id
    const int warp = t >> 5, lane = t & 31;

    // ---- occupancy decode ----
    const int b = occ_raw[t];
    // encoding: byte-bool -> 154 nonzero bytes (>128); widened 32-bit bool
    // (int32 or float32) -> first 512 bytes cover 128 cells, <=128 nonzero.
    const int nz = __syncthreads_count(b != 0);
    int v;
    if (nz > 128) v = (b != 0);
    else          v = (reinterpret_cast<const unsigned int*>(occ_raw)[t] != 0u);

    const unsigned int bal = __ballot_sync(0xffffffffu, v);
    if (lane == 0) words[warp] = bal;
    __syncthreads();

    // warp 0: exclusive scan of 16 word-popcounts
    if (warp == 0 && lane < 16) {
        int p = __popc(words[lane]);
        int sum = p;
        #pragma unroll
        for (int o = 1; o < 16; o <<= 1) {
            int nb = __shfl_up_sync(0x0000ffffu, sum, o, 16);
            if (lane >= o) sum += nb;
        }
        pre[lane] = sum - p;             // exclusive
    }
    __syncthreads();

    // ---- gather: one spatial float4 cell, 7 j-channels (jc = j*28 + c) ----
    const int id = blockIdx.x * 512 + t;   // < 1,835,008

    const int zi = id & 15;              // z = 4*zi -> dense 512B warp stores
    int tmp = id >> 4;
    const int y = tmp & 63;  tmp >>= 6;
    const int x = tmp & 63;  tmp >>= 6;
    const int c = tmp;                   // 0..27

    const int gz = (zi << 2) + OFF;
    const int gy = y + OFF;
    const int gx = x + OFF;
    const int tz = gz >> 4, iz = gz & 15;
    const int ty = gy >> 4, iy = gy & 15;
    const int tx = gx >> 4, ix = gx & 15;

    // inline LUT: tile index for this thread's cell only
    const int lin = ((tx << 3) + ty) * 8 + tz;   // 8x8x8 flat cell id
    const int w = lin >> 5, bit = lin & 31;
    const unsigned int wd = words[w];
    const int occ_bit = (wd >> bit) & 1;
    const int tidx = pre[w] + __popc(wd & ((1u << bit) - 1u));

    const int spatial_src = (ix << 8) + (iy << 4) + iz;      // float offset in slab
    const int spatial_out = (x << 10) + (y << 4) + zi;       // float4 offset in jc

    float4 v4[7];
    #pragma unroll
    for (int j = 0; j < 7; j++) v4[j] = make_float4(0.f, 0.f, 0.f, 0.f);

    if (occ_bit) {
        const float4* base = reinterpret_cast<const float4*>(
            tiles + (size_t)(tidx * JC + c) * TILE_STRIDE + spatial_src);
        const size_t st = (size_t)NC * TILE_STRIDE / 4;      // float4 stride per j
        #pragma unroll
        for (int j = 0; j < 7; j++) v4[j] = __ldcs(base + j * st);
    }

    float4* o = out + spatial_out + (size_t)c * OUT_JC_F4;
    const size_t ot = (size_t)NC * OUT_JC_F4;
    #pragma unroll
    for (int j = 0; j < 7; j++) __stcs(o + j * ot, v4[j]);
}

extern "C" void kernel_launch(void* const* d_in, const int* in_sizes, int n_in,
                              void* d_out, int out_size) {
    const float* tiles = (const float*)d_in[0];
    const unsigned char* occ = (const unsigned char*)d_in[1];

    gather_kernel<<<N_THREADS / 512, 512>>>(tiles, occ, (float4*)d_out);
}

// round 17
// speedup vs baseline: 1.1649x; 1.0464x over previous
#include <cuda_runtime.h>

// tiles: (154, 7, 28, 16, 16, 16) fp32
// occupancy: (8,8,8) bool (encoding auto-detected)
// output: (7, 1, 28, 64, 64, 64) fp32 == (196, 64, 64, 64), window offset 8, 5x5x5 tiles
#define NT 5
#define OFF 8
#define JC 196
#define NC 28                 // c = 0..27 in thread id; j = 0..6 unrolled (MLP=7)
#define TILE_STRIDE 4096      // 16^3 floats per (tile,jc) slab
#define OUT_JC_F4 65536       // 64*64*64/4 float4 per jc
#define N_THREADS (NC * 64 * 64 * 16)   // 1,835,008 -> 7168 blocks

__device__ int g_lut[NT * NT * NT];
// 0 initially. Block 0 recomputes g_lut from the inputs on EVERY call, then
// sets the flag; other blocks wait for it. After call 1 the flag stays set
// (steady-state poll = one overlapped L2 read per block). Rewrite races are
// benign (identical values from identical inputs) -> output never depends on
// call history.
__device__ unsigned int g_flag;

__global__ void __launch_bounds__(256) gather_kernel(
    const float* __restrict__ tiles,
    const unsigned char* __restrict__ occ_raw,
    float4* __restrict__ out) {

    const int t = threadIdx.x;

    if (blockIdx.x == 0) {
        // ---- build LUT: ballot/popcount over 512 cells (threads t, t+256) ----
        __shared__ unsigned int words[16];
        const int warp = t >> 5, lane = t & 31;

        const int b0 = occ_raw[t];
        const int b1 = occ_raw[t + 256];
        // encoding: byte-bool -> 154 nonzero bytes (>128); widened 32-bit bool
        // (int32/float32) -> first 512 bytes cover 128 cells -> <=128 nonzero.
        const int nz = __syncthreads_count((b0 != 0) || (b1 != 0) ? 1 : 0) +
                       __syncthreads_count((b0 != 0) && (b1 != 0) ? 1 : 0);
        int v0, v1;
        if (nz > 128) {
            v0 = (b0 != 0); v1 = (b1 != 0);
        } else {
            const unsigned int* w32 = reinterpret_cast<const unsigned int*>(occ_raw);
            v0 = (w32[t] != 0u); v1 = (w32[t + 256] != 0u);
        }
        const unsigned int bal0 = __ballot_sync(0xffffffffu, v0);
        const unsigned int bal1 = __ballot_sync(0xffffffffu, v1);
        if (lane == 0) { words[warp] = bal0; words[warp + 8] = bal1; }
        __syncthreads();

        const unsigned int lmask = (1u << lane) - 1u;
        int pre0 = 0, pre1 = 0;
        #pragma unroll
        for (int i = 0; i < 16; i++) {
            const int p = __popc(words[i]);
            pre0 += (i < warp) ? p : 0;
            pre1 += (i < warp + 8) ? p : 0;
        }
        const int idx0 = pre0 + __popc(words[warp] & lmask);
        const int idx1 = pre1 + __popc(words[warp + 8] & lmask);

        {
            int cx = t >> 6, cy = (t >> 3) & 7, cz = t & 7;
            if (cx < NT && cy < NT && cz < NT)
                g_lut[(cx * NT + cy) * NT + cz] = v0 ? idx0 : -1;
            const int u = t + 256;
            cx = u >> 6; cy = (u >> 3) & 7; cz = u & 7;
            if (cx < NT && cy < NT && cz < NT)
                g_lut[(cx * NT + cy) * NT + cz] = v1 ? idx1 : -1;
        }
        __syncthreads();
        if (t == 0) {
            __threadfence();
            atomicExch(&g_flag, 1u);     // release: LUT visible before flag
        }
        __syncthreads();
    } else {
        if (t == 0) {
            // acquire: volatile L2 read poll; one read in steady state
            const volatile unsigned int* f = &g_flag;
            while (*f == 0u) __nanosleep(64);
        }
        __syncthreads();
    }

    // ---- gather: one spatial float4 cell, 7 j-channels (jc = j*28 + c) ----
    const int id = blockIdx.x * 256 + t;   // < 1,835,008

    const int zi = id & 15;              // z = 4*zi -> dense 512B warp stores
    int tmp = id >> 4;
    const int y = tmp & 63;  tmp >>= 6;
    const int x = tmp & 63;  tmp >>= 6;
    const int c = tmp;                   // 0..27

    const int gz = (zi << 2) + OFF;
    const int gy = y + OFF;
    const int gx = x + OFF;
    const int tz = gz >> 4, iz = gz & 15;
    const int ty = gy >> 4, iy = gy & 15;
    const int tx = gx >> 4, ix = gx & 15;

    const int tidx = g_lut[(tx * NT + ty) * NT + tz];
    const int spatial_src = (ix << 8) + (iy << 4) + iz;      // float offset in slab
    const int spatial_out = (x << 10) + (y << 4) + zi;       // float4 offset in jc

    float4 v[7];
    #pragma unroll
    for (int j = 0; j < 7; j++) v[j] = make_float4(0.f, 0.f, 0.f, 0.f);

    if (tidx >= 0) {
        const float4* base = reinterpret_cast<const float4*>(
            tiles + (size_t)(tidx * JC + c) * TILE_STRIDE + spatial_src);
        const size_t st = (size_t)NC * TILE_STRIDE / 4;      // float4 stride per j
        #pragma unroll
        for (int j = 0; j < 7; j++) v[j] = __ldcs(base + j * st);
    }

    float4* o = out + spatial_out + (size_t)c * OUT_JC_F4;
    const size_t ot = (size_t)NC * OUT_JC_F4;
    #pragma unroll
    for (int j = 0; j < 7; j++) __stcs(o + j * ot, v[j]);
}

extern "C" void kernel_launch(void* const* d_in, const int* in_sizes, int n_in,
                              void* d_out, int out_size) {
    const float* tiles = (const float*)d_in[0];
    const unsigned char* occ = (const unsigned char*)d_in[1];

    gather_kernel<<<N_THREADS / 256, 256>>>(tiles, occ, (float4*)d_out);
}